// round 10
// baseline (speedup 1.0000x reference)
#include <cuda_runtime.h>
#include <cuda_bf16.h>

#define NN 50000
#define NE 640000
#define RK 128
#define NG 50
#define LN_EPS 1e-5f
#define CAP 96          // per-dst bucket capacity (in-degree ~ Poisson(12.8))

// ---------------- zero-initialized prep block (single memset) ---------------
struct __align__(16) PrepZero {
    int cnt_in[NN];     // in-degree / bucket fill counters
    int deg_out[NN];    // out-degree
    int mark0[NN];
    int mark1[NN];
    int mtgt[NN];       // target bitmap
    int count0;
    int count1;
    int pad[2];
};
__device__ PrepZero g_z;

// ---------------- scratch ----------------------------------------------------
__device__ float g_bufA[NN * RK];    // feats1 (valid at N0 rows)
__device__ float g_bufB[NN * RK];    // feats2 (valid at N1 rows)
__device__ float g_inv_in[NN];
__device__ float g_inv_out[NN];
__device__ int   g_bucket[NN * CAP]; // src ids bucketed by dst (19.2MB)
__device__ int   g_tgt[NG];
__device__ int   g_n0[NN];
__device__ int   g_n1[NN];

// ---------------- f32x2 helpers ---------------------------------------------
__device__ __forceinline__ unsigned long long pack2_dup(float x) {
    unsigned long long r;
    unsigned int u = __float_as_uint(x);
    asm("mov.b64 %0, {%1, %1};" : "=l"(r) : "r"(u));
    return r;
}
__device__ __forceinline__ unsigned long long fma2(unsigned long long a,
                                                   unsigned long long b,
                                                   unsigned long long c) {
    unsigned long long d;
    asm("fma.rn.f32x2 %0, %1, %2, %3;" : "=l"(d) : "l"(a), "l"(b), "l"(c));
    return d;
}
__device__ __forceinline__ void unpack2(unsigned long long v, float& a, float& b) {
    unsigned int lo, hi;
    asm("mov.b64 {%0, %1}, %2;" : "=r"(lo), "=r"(hi) : "l"(v));
    a = __uint_as_float(lo);
    b = __uint_as_float(hi);
}

// ---------------- targets init ----------------------------------------------
__global__ void tgt_init_kernel(const int* __restrict__ bnn) {
    __shared__ int sb[64];
    int t = threadIdx.x;
    if (t < 64) sb[t] = (t < NG) ? bnn[t] : 0;
    __syncthreads();
    if (t == 0) {
        int base = 0;
        for (int i = 0; i < NG; i++) {
            g_tgt[i] = base;
            g_z.mtgt[base] = 1;
            base += sb[i];
        }
    }
}

// ---------------- combined edge pass (2 x NE threads, one launch) ------------
// Threads [0, NE): bucket scatter.  Threads [NE, 2*NE): out-degree + N1.
__global__ void edge_kernel(const int* __restrict__ src, const int* __restrict__ dst) {
    int i = blockIdx.x * blockDim.x + threadIdx.x;
    if (i < NE) {
        int d = __ldg(dst + i);
        int slot = atomicAdd(&g_z.cnt_in[d], 1);
        if (slot < CAP) g_bucket[d * CAP + slot] = __ldg(src + i);
    } else if (i < 2 * NE) {
        int e = i - NE;
        int s = __ldg(src + e);
        atomicAdd(&g_z.deg_out[s], 1);   // no-return -> RED
        if (g_z.mtgt[__ldg(dst + e)]) {
            if (atomicExch(&g_z.mark1[s], 1) == 0) {
                int p = atomicAdd(&g_z.count1, 1);
                g_n1[p] = s;
            }
        }
    }
}

// ---------------- inv factors + N0 = in-neighbors of N1 ----------------------
__global__ void front0_inv_kernel() {
    int g0 = blockIdx.x * blockDim.x + threadIdx.x;
    int ntot = gridDim.x * blockDim.x;
    for (int i = g0; i < NN; i += ntot) {
        g_inv_in[i]  = rsqrtf(fmaxf((float)g_z.cnt_in[i], 1.0f));
        g_inv_out[i] = rsqrtf(fmaxf((float)g_z.deg_out[i], 1.0f));
    }
    int lane = threadIdx.x & 31;
    int w = g0 >> 5;
    int nw = ntot >> 5;
    int cnt1 = g_z.count1;
    for (int i = w; i < cnt1; i += nw) {
        int node = g_n1[i];
        int c = min(g_z.cnt_in[node], CAP);
        for (int e = lane; e < c; e += 32) {
            int s = g_bucket[node * CAP + e];
            if (atomicExch(&g_z.mark0[s], 1) == 0) {
                int p = atomicAdd(&g_z.count0, 1);
                g_n0[p] = s;
            }
        }
    }
}

// ---------------- fused layer: agg + GEMM + inv_in + bias + LN + ReLU --------
// Tile = 32 list nodes / block iteration. Phase A: 8 warps aggregate 4 nodes
// each into Ash. Phase B: GEMM from Ash (f32x2); thread (tr,tc) does rows
// {2tr,2tr+1} x cols [8tc,8tc+8); LN over the 16-lane row subgroup.
#define LAYER_SMEM ((RK * RK + 32 * 129) * 4)

__global__ void __launch_bounds__(256, 1)
layer_kernel(int level,   // 0: n0/count0   1: n1/count1   2: tgt/NG
             const float* __restrict__ IN,
             const float* __restrict__ W, const float* __restrict__ b,
             const float* __restrict__ gamma, const float* __restrict__ beta,
             float* __restrict__ OUT) {
    extern __shared__ float sm[];
    float* Wsh = sm;               // 128x128
    float* Ash = sm + RK * RK;     // 32x129
    __shared__ int ridx[32];

    const int tid = threadIdx.x;
    const int lane = tid & 31;
    const int wid = tid >> 5;

    const int* list = (level == 0) ? g_n0 : ((level == 1) ? g_n1 : g_tgt);
    const int cnt = (level == 0) ? g_z.count0 : ((level == 1) ? g_z.count1 : NG);
    const int outIsIdx = (level == 2);

    {
        const float4* Wg = (const float4*)W;
        float4* Ws4 = (float4*)Wsh;
        #pragma unroll
        for (int j = 0; j < 16; j++) Ws4[tid + j * 256] = Wg[tid + j * 256];
    }
    const int tc = tid & 15;
    const int tr = tid >> 4;
    float4 b0 = ((const float4*)b)[tc * 2];
    float4 b1 = ((const float4*)b)[tc * 2 + 1];
    float4 gm0 = ((const float4*)gamma)[tc * 2];
    float4 gm1 = ((const float4*)gamma)[tc * 2 + 1];
    float4 bt0 = ((const float4*)beta)[tc * 2];
    float4 bt1 = ((const float4*)beta)[tc * 2 + 1];

    const float4* IN4 = (const float4*)IN;
    int ntiles = (cnt + 31) / 32;

    for (int t = blockIdx.x; t < ntiles; t += gridDim.x) {
        __syncthreads();
        if (tid < 32) {
            int gi = t * 32 + tid;
            ridx[tid] = (gi < cnt) ? list[gi] : -1;
        }
        __syncthreads();

        // Phase A: aggregation — warp handles rows wid, wid+8, wid+16, wid+24
        #pragma unroll
        for (int rr = 0; rr < 4; rr++) {
            int row = wid + rr * 8;
            int node = ridx[row];
            float ax = 0.f, ay = 0.f, az = 0.f, aw = 0.f;
            if (node >= 0) {
                int deg = min(g_z.cnt_in[node], CAP);
                int base = node * CAP;
                for (int eb = 0; eb < deg; eb += 32) {
                    int c = min(32, deg - eb);
                    int se = 0; float io = 0.f;
                    if (lane < c) {
                        se = g_bucket[base + eb + lane];
                        io = g_inv_out[se];
                    }
                    for (int j = 0; j < c; j++) {
                        int s = __shfl_sync(0xffffffffu, se, j);
                        float wv = __shfl_sync(0xffffffffu, io, j);
                        float4 v = IN4[s * 32 + lane];
                        ax = fmaf(v.x, wv, ax);
                        ay = fmaf(v.y, wv, ay);
                        az = fmaf(v.z, wv, az);
                        aw = fmaf(v.w, wv, aw);
                    }
                }
            }
            float* p = Ash + row * 129 + lane * 4;
            p[0] = ax; p[1] = ay; p[2] = az; p[3] = aw;
        }
        __syncthreads();

        // Phase B: GEMM + epilogue
        unsigned long long acc[2][4];
        #pragma unroll
        for (int r = 0; r < 2; r++)
            #pragma unroll
            for (int p = 0; p < 4; p++) acc[r][p] = 0ULL;

        const float* a0 = Ash + (tr * 2) * 129;
        const float* a1 = Ash + (tr * 2 + 1) * 129;
        const float* wb = Wsh + tc * 8;
        #pragma unroll 4
        for (int k = 0; k < RK; k++) {
            ulonglong2 wA = *(const ulonglong2*)(wb + k * RK);
            ulonglong2 wB = *(const ulonglong2*)(wb + k * RK + 4);
            unsigned long long av0 = pack2_dup(a0[k]);
            unsigned long long av1 = pack2_dup(a1[k]);
            acc[0][0] = fma2(av0, wA.x, acc[0][0]);
            acc[0][1] = fma2(av0, wA.y, acc[0][1]);
            acc[0][2] = fma2(av0, wB.x, acc[0][2]);
            acc[0][3] = fma2(av0, wB.y, acc[0][3]);
            acc[1][0] = fma2(av1, wA.x, acc[1][0]);
            acc[1][1] = fma2(av1, wA.y, acc[1][1]);
            acc[1][2] = fma2(av1, wB.x, acc[1][2]);
            acc[1][3] = fma2(av1, wB.y, acc[1][3]);
        }

        #pragma unroll
        for (int r = 0; r < 2; r++) {
            int row = tr * 2 + r;
            int gr = ridx[row];
            float inv = (gr >= 0) ? g_inv_in[gr] : 1.f;
            float v[8];
            unpack2(acc[r][0], v[0], v[1]);
            unpack2(acc[r][1], v[2], v[3]);
            unpack2(acc[r][2], v[4], v[5]);
            unpack2(acc[r][3], v[6], v[7]);
            v[0] = v[0] * inv + b0.x; v[1] = v[1] * inv + b0.y;
            v[2] = v[2] * inv + b0.z; v[3] = v[3] * inv + b0.w;
            v[4] = v[4] * inv + b1.x; v[5] = v[5] * inv + b1.y;
            v[6] = v[6] * inv + b1.z; v[7] = v[7] * inv + b1.w;

            float s = v[0] + v[1] + v[2] + v[3] + v[4] + v[5] + v[6] + v[7];
            #pragma unroll
            for (int o = 8; o; o >>= 1) s += __shfl_xor_sync(0xffffffffu, s, o);
            float mean = s * (1.0f / 128.0f);
            float ss = 0.f;
            #pragma unroll
            for (int q = 0; q < 8; q++) { float c = v[q] - mean; ss += c * c; }
            #pragma unroll
            for (int o = 8; o; o >>= 1) ss += __shfl_xor_sync(0xffffffffu, ss, o);
            float rstd = rsqrtf(ss * (1.0f / 128.0f) + LN_EPS);

            if (gr >= 0) {
                float* op = outIsIdx ? (OUT + (t * 32 + row) * RK)
                                     : (OUT + gr * RK);
                float4 o0, o1;
                o0.x = fmaxf((v[0] - mean) * rstd * gm0.x + bt0.x, 0.f);
                o0.y = fmaxf((v[1] - mean) * rstd * gm0.y + bt0.y, 0.f);
                o0.z = fmaxf((v[2] - mean) * rstd * gm0.z + bt0.z, 0.f);
                o0.w = fmaxf((v[3] - mean) * rstd * gm0.w + bt0.w, 0.f);
                o1.x = fmaxf((v[4] - mean) * rstd * gm1.x + bt1.x, 0.f);
                o1.y = fmaxf((v[5] - mean) * rstd * gm1.y + bt1.y, 0.f);
                o1.z = fmaxf((v[6] - mean) * rstd * gm1.z + bt1.z, 0.f);
                o1.w = fmaxf((v[7] - mean) * rstd * gm1.w + bt1.w, 0.f);
                *(float4*)(op + tc * 8) = o0;
                *(float4*)(op + tc * 8 + 4) = o1;
            }
        }
    }
}

// ---------------- launch: single stream, 7 nodes, no events ------------------
extern "C" void kernel_launch(void* const* d_in, const int* in_sizes, int n_in,
                              void* d_out, int out_size) {
    const float* features = (const float*)d_in[0];
    const int*   src      = (const int*)d_in[1];
    const int*   dst      = (const int*)d_in[2];
    const int*   bnn      = (const int*)d_in[3];
    const float* Ws       = (const float*)d_in[4];
    const float* bs       = (const float*)d_in[5];
    const float* gammas   = (const float*)d_in[6];
    const float* betas    = (const float*)d_in[7];
    float* out = (float*)d_out;

    cudaFuncSetAttribute(layer_kernel, cudaFuncAttributeMaxDynamicSharedMemorySize,
                         LAYER_SMEM);

    void* zp = nullptr;
    cudaGetSymbolAddress(&zp, g_z);
    cudaMemsetAsync(zp, 0, sizeof(PrepZero), 0);

    tgt_init_kernel<<<1, 64>>>(bnn);
    edge_kernel<<<(2 * NE + 255) / 256, 256>>>(src, dst);
    front0_inv_kernel<<<148, 256>>>();

    layer_kernel<<<148, 256, LAYER_SMEM>>>(0, features, Ws, bs, gammas, betas,
                                           g_bufA);
    layer_kernel<<<32, 256, LAYER_SMEM>>>(1, g_bufA, Ws + RK * RK, bs + RK,
                                          gammas + RK, betas + RK, g_bufB);
    layer_kernel<<<2, 256, LAYER_SMEM>>>(2, g_bufB, Ws + 2 * RK * RK,
                                         bs + 2 * RK, gammas + 2 * RK,
                                         betas + 2 * RK, out);
}

// round 13
// speedup vs baseline: 1.0466x; 1.0466x over previous
#include <cuda_runtime.h>
#include <cuda_bf16.h>

#define NN 50000
#define NE 640000
#define RK 128
#define NG 50
#define LN_EPS 1e-5f
#define CAP 96          // per-dst bucket capacity (in-degree ~ Poisson(12.8))

// ---------------- zero-initialized prep block (single memset) ---------------
struct __align__(16) PrepZero {
    int cnt_in[NN];     // in-degree / bucket fill counters
    int deg_out[NN];    // out-degree
    int mark0[NN];
    int mark1[NN];
    int mtgt[NN];       // target bitmap
    int count0;
    int count1;
    int pad[2];
};
__device__ PrepZero g_z;

// ---------------- scratch ----------------------------------------------------
__device__ float g_h[NN * RK];       // L0 aggregation results (by node id)
__device__ float g_bufA[NN * RK];    // feats1 (valid at N0 rows)
__device__ float g_bufB[NN * RK];    // feats2 (valid at N1 rows)
__device__ float g_inv_in[NN];
__device__ float g_inv_out[NN];
__device__ int   g_bucket[NN * CAP]; // src ids bucketed by dst (19.2MB)
__device__ int   g_tgt[NG];
__device__ int   g_n0[NN];
__device__ int   g_n1[NN];

// ---------------- f32x2 helpers ---------------------------------------------
__device__ __forceinline__ unsigned long long pack2_dup(float x) {
    unsigned long long r;
    unsigned int u = __float_as_uint(x);
    asm("mov.b64 %0, {%1, %1};" : "=l"(r) : "r"(u));
    return r;
}
__device__ __forceinline__ unsigned long long fma2(unsigned long long a,
                                                   unsigned long long b,
                                                   unsigned long long c) {
    unsigned long long d;
    asm("fma.rn.f32x2 %0, %1, %2, %3;" : "=l"(d) : "l"(a), "l"(b), "l"(c));
    return d;
}
__device__ __forceinline__ void unpack2(unsigned long long v, float& a, float& b) {
    unsigned int lo, hi;
    asm("mov.b64 {%0, %1}, %2;" : "=r"(lo), "=r"(hi) : "l"(v));
    a = __uint_as_float(lo);
    b = __uint_as_float(hi);
}

// ---------------- targets init ----------------------------------------------
__global__ void tgt_init_kernel(const int* __restrict__ bnn) {
    __shared__ int sb[64];
    int t = threadIdx.x;
    if (t < 64) sb[t] = (t < NG) ? bnn[t] : 0;
    __syncthreads();
    if (t == 0) {
        int base = 0;
        for (int i = 0; i < NG; i++) {
            g_tgt[i] = base;
            g_z.mtgt[base] = 1;
            base += sb[i];
        }
    }
}

// ---------------- combined edge pass (2 x NE threads, one launch) ------------
__global__ void edge_kernel(const int* __restrict__ src, const int* __restrict__ dst) {
    int i = blockIdx.x * blockDim.x + threadIdx.x;
    if (i < NE) {
        int d = __ldg(dst + i);
        int slot = atomicAdd(&g_z.cnt_in[d], 1);
        if (slot < CAP) g_bucket[d * CAP + slot] = __ldg(src + i);
    } else if (i < 2 * NE) {
        int e = i - NE;
        int s = __ldg(src + e);
        atomicAdd(&g_z.deg_out[s], 1);
        if (g_z.mtgt[__ldg(dst + e)]) {
            if (atomicExch(&g_z.mark1[s], 1) == 0) {
                int p = atomicAdd(&g_z.count1, 1);
                g_n1[p] = s;
            }
        }
    }
}

// ---------------- inv factors + N0 = in-neighbors of N1 ----------------------
__global__ void front0_inv_kernel() {
    int g0 = blockIdx.x * blockDim.x + threadIdx.x;
    int ntot = gridDim.x * blockDim.x;
    for (int i = g0; i < NN; i += ntot) {
        g_inv_in[i]  = rsqrtf(fmaxf((float)g_z.cnt_in[i], 1.0f));
        g_inv_out[i] = rsqrtf(fmaxf((float)g_z.deg_out[i], 1.0f));
    }
    int lane = threadIdx.x & 31;
    int w = g0 >> 5;
    int nw = ntot >> 5;
    int cnt1 = g_z.count1;
    for (int i = w; i < cnt1; i += nw) {
        int node = g_n1[i];
        int c = min(g_z.cnt_in[node], CAP);
        for (int e = lane; e < c; e += 32) {
            int s = g_bucket[node * CAP + e];
            if (atomicExch(&g_z.mark0[s], 1) == 0) {
                int p = atomicAdd(&g_z.count0, 1);
                g_n0[p] = s;
            }
        }
    }
}

// ---------------- L0 aggregation: one warp per N0 node, full occupancy -------
// R10-exact gather loop; output indexed BY NODE ID into g_h.
__global__ void __launch_bounds__(256)
agg0_kernel(const float* __restrict__ IN) {
    const float4* IN4 = (const float4*)IN;
    int lane = threadIdx.x & 31;
    int w = (blockIdx.x * blockDim.x + threadIdx.x) >> 5;
    int nw = (gridDim.x * blockDim.x) >> 5;
    int cnt = g_z.count0;
    for (int i = w; i < cnt; i += nw) {
        int node = g_n0[i];
        int deg = min(g_z.cnt_in[node], CAP);
        int base = node * CAP;
        float ax = 0.f, ay = 0.f, az = 0.f, aw = 0.f;
        for (int eb = 0; eb < deg; eb += 32) {
            int c = min(32, deg - eb);
            int se = 0; float io = 0.f;
            if (lane < c) {
                se = g_bucket[base + eb + lane];
                io = g_inv_out[se];
            }
            for (int j = 0; j < c; j++) {
                int s = __shfl_sync(0xffffffffu, se, j);
                float wv = __shfl_sync(0xffffffffu, io, j);
                float4 v = IN4[s * 32 + lane];
                ax = fmaf(v.x, wv, ax);
                ay = fmaf(v.y, wv, ay);
                az = fmaf(v.z, wv, az);
                aw = fmaf(v.w, wv, aw);
            }
        }
        ((float4*)g_h)[node * 32 + lane] = make_float4(ax, ay, az, aw);
    }
}

// ---------------- layer kernel (R10 structure) -------------------------------
// level 0: Phase A = dense row load from g_h (global, by node id via ridx)
// level 1/2: Phase A = R10-exact bucket gather from IN
#define LAYER_SMEM ((RK * RK + 32 * 129) * 4)

__global__ void __launch_bounds__(256, 1)
layer_kernel(int level,   // 0: n0/count0   1: n1/count1   2: tgt/NG
             const float* __restrict__ IN,
             const float* __restrict__ W, const float* __restrict__ b,
             const float* __restrict__ gamma, const float* __restrict__ beta,
             float* __restrict__ OUT) {
    extern __shared__ float sm[];
    float* Wsh = sm;               // 128x128
    float* Ash = sm + RK * RK;     // 32x129
    __shared__ int ridx[32];

    const int tid = threadIdx.x;
    const int lane = tid & 31;
    const int wid = tid >> 5;

    const int* list = (level == 0) ? g_n0 : ((level == 1) ? g_n1 : g_tgt);
    const int cnt = (level == 0) ? g_z.count0 : ((level == 1) ? g_z.count1 : NG);
    const int outIsIdx = (level == 2);

    {
        const float4* Wg = (const float4*)W;
        float4* Ws4 = (float4*)Wsh;
        #pragma unroll
        for (int j = 0; j < 16; j++) Ws4[tid + j * 256] = Wg[tid + j * 256];
    }
    const int tc = tid & 15;
    const int tr = tid >> 4;
    float4 b0 = ((const float4*)b)[tc * 2];
    float4 b1 = ((const float4*)b)[tc * 2 + 1];
    float4 gm0 = ((const float4*)gamma)[tc * 2];
    float4 gm1 = ((const float4*)gamma)[tc * 2 + 1];
    float4 bt0 = ((const float4*)beta)[tc * 2];
    float4 bt1 = ((const float4*)beta)[tc * 2 + 1];

    const float4* IN4 = (const float4*)IN;
    const float4* H4 = (const float4*)g_h;   // device-side global reference
    int ntiles = (cnt + 31) / 32;

    for (int t = blockIdx.x; t < ntiles; t += gridDim.x) {
        __syncthreads();
        if (tid < 32) {
            int gi = t * 32 + tid;
            ridx[tid] = (gi < cnt) ? list[gi] : -1;
        }
        __syncthreads();

        // Phase A
        if (level == 0) {
            // dense coalesced row load from g_h by node id
            int row = tid >> 3;
            int gr = ridx[row];
            int c0 = (tid & 7) * 4;
            float* pd = Ash + row * 129;
            #pragma unroll
            for (int q = 0; q < 4; q++) {
                float4 v = make_float4(0.f, 0.f, 0.f, 0.f);
                if (gr >= 0) v = H4[gr * 32 + c0 + q];
                float* p = pd + (c0 + q) * 4;
                p[0] = v.x; p[1] = v.y; p[2] = v.z; p[3] = v.w;
            }
        } else {
            // R10-exact gather: warp handles rows wid, wid+8, wid+16, wid+24
            #pragma unroll
            for (int rr = 0; rr < 4; rr++) {
                int row = wid + rr * 8;
                int node = ridx[row];
                float ax = 0.f, ay = 0.f, az = 0.f, aw = 0.f;
                if (node >= 0) {
                    int deg = min(g_z.cnt_in[node], CAP);
                    int base = node * CAP;
                    for (int eb = 0; eb < deg; eb += 32) {
                        int c = min(32, deg - eb);
                        int se = 0; float io = 0.f;
                        if (lane < c) {
                            se = g_bucket[base + eb + lane];
                            io = g_inv_out[se];
                        }
                        for (int j = 0; j < c; j++) {
                            int s = __shfl_sync(0xffffffffu, se, j);
                            float wv = __shfl_sync(0xffffffffu, io, j);
                            float4 v = IN4[s * 32 + lane];
                            ax = fmaf(v.x, wv, ax);
                            ay = fmaf(v.y, wv, ay);
                            az = fmaf(v.z, wv, az);
                            aw = fmaf(v.w, wv, aw);
                        }
                    }
                }
                float* p = Ash + row * 129 + lane * 4;
                p[0] = ax; p[1] = ay; p[2] = az; p[3] = aw;
            }
        }
        __syncthreads();

        // Phase B: GEMM + epilogue
        unsigned long long acc[2][4];
        #pragma unroll
        for (int r = 0; r < 2; r++)
            #pragma unroll
            for (int p = 0; p < 4; p++) acc[r][p] = 0ULL;

        const float* a0 = Ash + (tr * 2) * 129;
        const float* a1 = Ash + (tr * 2 + 1) * 129;
        const float* wb = Wsh + tc * 8;
        #pragma unroll 4
        for (int k = 0; k < RK; k++) {
            ulonglong2 wA = *(const ulonglong2*)(wb + k * RK);
            ulonglong2 wB = *(const ulonglong2*)(wb + k * RK + 4);
            unsigned long long av0 = pack2_dup(a0[k]);
            unsigned long long av1 = pack2_dup(a1[k]);
            acc[0][0] = fma2(av0, wA.x, acc[0][0]);
            acc[0][1] = fma2(av0, wA.y, acc[0][1]);
            acc[0][2] = fma2(av0, wB.x, acc[0][2]);
            acc[0][3] = fma2(av0, wB.y, acc[0][3]);
            acc[1][0] = fma2(av1, wA.x, acc[1][0]);
            acc[1][1] = fma2(av1, wA.y, acc[1][1]);
            acc[1][2] = fma2(av1, wB.x, acc[1][2]);
            acc[1][3] = fma2(av1, wB.y, acc[1][3]);
        }

        #pragma unroll
        for (int r = 0; r < 2; r++) {
            int row = tr * 2 + r;
            int gr = ridx[row];
            float inv = (gr >= 0) ? g_inv_in[gr] : 1.f;
            float v[8];
            unpack2(acc[r][0], v[0], v[1]);
            unpack2(acc[r][1], v[2], v[3]);
            unpack2(acc[r][2], v[4], v[5]);
            unpack2(acc[r][3], v[6], v[7]);
            v[0] = v[0] * inv + b0.x; v[1] = v[1] * inv + b0.y;
            v[2] = v[2] * inv + b0.z; v[3] = v[3] * inv + b0.w;
            v[4] = v[4] * inv + b1.x; v[5] = v[5] * inv + b1.y;
            v[6] = v[6] * inv + b1.z; v[7] = v[7] * inv + b1.w;

            float s = v[0] + v[1] + v[2] + v[3] + v[4] + v[5] + v[6] + v[7];
            #pragma unroll
            for (int o = 8; o; o >>= 1) s += __shfl_xor_sync(0xffffffffu, s, o);
            float mean = s * (1.0f / 128.0f);
            float ss = 0.f;
            #pragma unroll
            for (int q = 0; q < 8; q++) { float c = v[q] - mean; ss += c * c; }
            #pragma unroll
            for (int o = 8; o; o >>= 1) ss += __shfl_xor_sync(0xffffffffu, ss, o);
            float rstd = rsqrtf(ss * (1.0f / 128.0f) + LN_EPS);

            if (gr >= 0) {
                float* op = outIsIdx ? (OUT + (t * 32 + row) * RK)
                                     : (OUT + gr * RK);
                float4 o0, o1;
                o0.x = fmaxf((v[0] - mean) * rstd * gm0.x + bt0.x, 0.f);
                o0.y = fmaxf((v[1] - mean) * rstd * gm0.y + bt0.y, 0.f);
                o0.z = fmaxf((v[2] - mean) * rstd * gm0.z + bt0.z, 0.f);
                o0.w = fmaxf((v[3] - mean) * rstd * gm0.w + bt0.w, 0.f);
                o1.x = fmaxf((v[4] - mean) * rstd * gm1.x + bt1.x, 0.f);
                o1.y = fmaxf((v[5] - mean) * rstd * gm1.y + bt1.y, 0.f);
                o1.z = fmaxf((v[6] - mean) * rstd * gm1.z + bt1.z, 0.f);
                o1.w = fmaxf((v[7] - mean) * rstd * gm1.w + bt1.w, 0.f);
                *(float4*)(op + tc * 8) = o0;
                *(float4*)(op + tc * 8 + 4) = o1;
            }
        }
    }
}

// ---------------- launch: single stream --------------------------------------
extern "C" void kernel_launch(void* const* d_in, const int* in_sizes, int n_in,
                              void* d_out, int out_size) {
    const float* features = (const float*)d_in[0];
    const int*   src      = (const int*)d_in[1];
    const int*   dst      = (const int*)d_in[2];
    const int*   bnn      = (const int*)d_in[3];
    const float* Ws       = (const float*)d_in[4];
    const float* bs       = (const float*)d_in[5];
    const float* gammas   = (const float*)d_in[6];
    const float* betas    = (const float*)d_in[7];
    float* out = (float*)d_out;

    cudaFuncSetAttribute(layer_kernel, cudaFuncAttributeMaxDynamicSharedMemorySize,
                         LAYER_SMEM);

    void* zp = nullptr;
    cudaGetSymbolAddress(&zp, g_z);
    cudaMemsetAsync(zp, 0, sizeof(PrepZero), 0);

    tgt_init_kernel<<<1, 64>>>(bnn);
    edge_kernel<<<(2 * NE + 255) / 256, 256>>>(src, dst);
    front0_inv_kernel<<<148, 256>>>();

    agg0_kernel<<<1184, 256>>>(features);
    layer_kernel<<<148, 256, LAYER_SMEM>>>(0, features, Ws, bs, gammas, betas,
                                           g_bufA);
    layer_kernel<<<32, 256, LAYER_SMEM>>>(1, g_bufA, Ws + RK * RK, bs + RK,
                                          gammas + RK, betas + RK, g_bufB);
    layer_kernel<<<2, 256, LAYER_SMEM>>>(2, g_bufB, Ws + 2 * RK * RK,
                                         bs + 2 * RK, gammas + 2 * RK,
                                         betas + 2 * RK, out);
}